// round 12
// baseline (speedup 1.0000x reference)
#include <cuda_runtime.h>
#include <cuda_fp16.h>

// ImageNormalization2D: x (8,1024,1024,2) f32, k=61 box local std-normalization.
// R12: all global transactions widened to 16B (2 channel-pairs per thread) in
//   all three passes; structure unchanged from R11 (V-chunked, H-scan, V-chunked).

#define NB 8
#define HB 1024
#define WB 1024
#define WH (WB/2)            // 512 double-width units per row
#define HALF_K 30
#define TOT (NB*HB*WB)       // channel-pair elements
#define CHUNK 4

#define NSEGA 32
#define SEGROWSA (HB / NSEGA)
#define NSEGC 16
#define SEGROWSC (HB / NSEGC)

static constexpr float SCALE_ = 1.0f / (61.0f * 61.0f * 2.0f);  // 1/(k*k*C)

// Scratch (static device globals; fp16x2 packed in unsigned)
__device__ unsigned g_v1[TOT];    // Vsum(x)                    32 MB
__device__ unsigned g_out[TOT];   // x - box(x)                 32 MB
__device__ uint2    g_u[TOT];     // {Hsum(out), Hsum(out^2)}   64 MB

static __device__ __forceinline__ int pad32(int j) { return j + (j >> 5); }
#define PAD8(j) ((j) + ((j) >> 3))

static __device__ __forceinline__ float2 h2f(unsigned u) {
    __half2 h; *reinterpret_cast<unsigned*>(&h) = u;
    return __half22float2(h);
}
static __device__ __forceinline__ unsigned f2h(float a, float b) {
    __half2 h = __floats2half2_rn(a, b);
    return *reinterpret_cast<unsigned*>(&h);
}

// --------------- Pass A: vertical window sum of x -> v1 (fp16) -----------------
// 2 channel-pairs per thread: float4 loads, uint2 stores.
__global__ void __launch_bounds__(128) pA_vsum(const float4* __restrict__ x4)
{
    const int g   = blockIdx.x * 128 + threadIdx.x;   // NB*WH*NSEGA threads
    const int wp  = g & (WH - 1);
    const int nw  = g >> 9;
    const int n   = nw & (NB - 1);
    const int seg = nw >> 3;                          // 0..NSEGA-1
    const int r0  = seg * SEGROWSA;
    const int base = (n * HB) * WH + wp;
    uint2* __restrict__ v1o = reinterpret_cast<uint2*>(g_v1);

    float sx0 = 0.f, sy0 = 0.f, sx1 = 0.f, sy1 = 0.f;
    #pragma unroll 6
    for (int j = 0; j <= 2 * HALF_K; ++j) {
        const int row = r0 - HALF_K - 1 + j;
        if (row >= 0) {
            float4 v = x4[base + row * WH];
            sx0 += v.x; sy0 += v.y; sx1 += v.z; sy1 += v.w;
        }
    }

    float4 avA[CHUNK], svA[CHUNK], avB[CHUNK], svB[CHUNK];

    auto loadC = [&](int c, float4* av, float4* sv) {
        #pragma unroll
        for (int q = 0; q < CHUNK; ++q) {
            const int r   = r0 + c + q;
            const int add = r + HALF_K;
            const int sub = r - HALF_K - 1;
            av[q] = (add < HB) ? x4[base + add * WH] : make_float4(0.f,0.f,0.f,0.f);
            sv[q] = (sub >= 0) ? x4[base + sub * WH] : make_float4(0.f,0.f,0.f,0.f);
        }
    };
    auto compC = [&](int c, const float4* av, const float4* sv) {
        #pragma unroll
        for (int q = 0; q < CHUNK; ++q) {
            sx0 += av[q].x - sv[q].x; sy0 += av[q].y - sv[q].y;
            sx1 += av[q].z - sv[q].z; sy1 += av[q].w - sv[q].w;
            v1o[base + (r0 + c + q) * WH] = make_uint2(f2h(sx0, sy0), f2h(sx1, sy1));
        }
    };

    loadC(0, avA, svA);
    #pragma unroll
    for (int c = 0; c < SEGROWSA; c += 2 * CHUNK) {
        loadC(c + CHUNK, avB, svB);
        compC(c, avA, svA);
        if (c + 2 * CHUNK < SEGROWSA)
            loadC(c + 2 * CHUNK, avA, svA);
        compC(c + CHUNK, avB, svB);
    }
}

// ------ Pass B: scan-based. out = x - Hbox(v1)*scale; u1,u2 = Hbox(out,out^2) --
// One image-row per 128-thread block. Smem ~22.9 KB. 16B global transactions.
__global__ void __launch_bounds__(128, 8) pB_hscan(const float4* __restrict__ x4)
{
    __shared__ float2   sPa[1160];   // P1, then P2   (PAD8: max idx 1150)
    __shared__ float2   sPb[1160];   // P3
    __shared__ unsigned sV[1056];    // v1 stage, then out (fp16)
    __shared__ float2   wsA[4];
    __shared__ float4   wsB[4];

    const int t    = threadIdx.x;       // 0..127
    const int lane = t & 31;
    const int wid  = t >> 5;
    const size_t base  = (size_t)blockIdx.x * WB;
    const size_t base4 = (size_t)blockIdx.x * WH;   // in 16B units

    // 1. stage v1 row via uint4 (256 per row)
    {
        const uint4* src = reinterpret_cast<const uint4*>(g_v1 + base);
        #pragma unroll
        for (int i = 0; i < 2; ++i) {
            const int idx = t + 128 * i;
            uint4 v = src[idx];
            const int col = 4 * idx;
            sV[pad32(col)]     = v.x;
            sV[pad32(col + 1)] = v.y;
            sV[pad32(col + 2)] = v.z;
            sV[pad32(col + 3)] = v.w;
        }
    }
    __syncthreads();

    // 2. scan v1 -> P1 (sPa). Contiguous ownership: thread t owns [8t, 8t+8).
    {
        float2 pref[8];
        float ax = 0.f, ay = 0.f;
        #pragma unroll
        for (int q = 0; q < 8; ++q) {
            float2 v = h2f(sV[pad32(8 * t + q)]);
            ax += v.x; ay += v.y;
            pref[q] = make_float2(ax, ay);
        }
        float tx = ax, ty = ay;
        #pragma unroll
        for (int d = 1; d < 32; d <<= 1) {
            float ox = __shfl_up_sync(0xffffffffu, tx, d);
            float oy = __shfl_up_sync(0xffffffffu, ty, d);
            if (lane >= d) { tx += ox; ty += oy; }
        }
        if (lane == 31) wsA[wid] = make_float2(tx, ty);
        __syncthreads();
        float bx = tx - ax, by = ty - ay;
        for (int k = 0; k < wid; ++k) { bx += wsA[k].x; by += wsA[k].y; }
        #pragma unroll
        for (int q = 0; q < 8; ++q)
            sPa[PAD8(8 * t + q)] = make_float2(bx + pref[q].x, by + pref[q].y);
    }
    __syncthreads();

    // 3. out = x - window(P1)*scale. 2 px/thread-iter: x float4, g_out uint2.
    {
        uint2* outd = reinterpret_cast<uint2*>(g_out + base);
        #pragma unroll
        for (int k = 0; k < 4; ++k) {
            const int idx = t + 128 * k;          // 0..511
            const int w0  = 2 * idx;
            const int w1  = w0 + 1;
            float4 xv = x4[base4 + idx];

            int hi0 = w0 + HALF_K; if (hi0 > WB - 1) hi0 = WB - 1;
            const int lo0 = w0 - HALF_K - 1;
            float2 m0 = sPa[PAD8(hi0)];
            if (lo0 >= 0) { float2 p = sPa[PAD8(lo0)]; m0.x -= p.x; m0.y -= p.y; }

            int hi1 = w1 + HALF_K; if (hi1 > WB - 1) hi1 = WB - 1;
            const int lo1 = w1 - HALF_K - 1;
            float2 m1 = sPa[PAD8(hi1)];
            if (lo1 >= 0) { float2 p = sPa[PAD8(lo1)]; m1.x -= p.x; m1.y -= p.y; }

            const unsigned o0 = f2h(xv.x - m0.x * SCALE_, xv.y - m0.y * SCALE_);
            const unsigned o1 = f2h(xv.z - m1.x * SCALE_, xv.w - m1.y * SCALE_);
            outd[idx] = make_uint2(o0, o1);
            sV[pad32(w0)] = o0;                   // v1 dead; repurpose as out
            sV[pad32(w1)] = o1;
        }
    }
    __syncthreads();

    // 4. dual scan of out, out^2 -> P2 (sPa), P3 (sPb)
    {
        float2 p1[8], p2[8];
        float a1x = 0.f, a1y = 0.f, a2x = 0.f, a2y = 0.f;
        #pragma unroll
        for (int q = 0; q < 8; ++q) {
            float2 v = h2f(sV[pad32(8 * t + q)]);
            a1x += v.x;       a1y += v.y;
            a2x += v.x * v.x; a2y += v.y * v.y;
            p1[q] = make_float2(a1x, a1y);
            p2[q] = make_float2(a2x, a2y);
        }
        float t1x = a1x, t1y = a1y, t2x = a2x, t2y = a2y;
        #pragma unroll
        for (int d = 1; d < 32; d <<= 1) {
            float o1x = __shfl_up_sync(0xffffffffu, t1x, d);
            float o1y = __shfl_up_sync(0xffffffffu, t1y, d);
            float o2x = __shfl_up_sync(0xffffffffu, t2x, d);
            float o2y = __shfl_up_sync(0xffffffffu, t2y, d);
            if (lane >= d) { t1x += o1x; t1y += o1y; t2x += o2x; t2y += o2y; }
        }
        if (lane == 31) wsB[wid] = make_float4(t1x, t1y, t2x, t2y);
        __syncthreads();
        float b1x = t1x - a1x, b1y = t1y - a1y;
        float b2x = t2x - a2x, b2y = t2y - a2y;
        for (int k = 0; k < wid; ++k) {
            float4 s = wsB[k];
            b1x += s.x; b1y += s.y; b2x += s.z; b2y += s.w;
        }
        #pragma unroll
        for (int q = 0; q < 8; ++q) {
            sPa[PAD8(8 * t + q)] = make_float2(b1x + p1[q].x, b1y + p1[q].y);
            sPb[PAD8(8 * t + q)] = make_float2(b2x + p2[q].x, b2y + p2[q].y);
        }
    }
    __syncthreads();

    // 5. u windows -> g_u via uint4 (2 columns per store)
    {
        uint4* ud = reinterpret_cast<uint4*>(g_u + base);
        #pragma unroll
        for (int k = 0; k < 4; ++k) {
            const int idx = t + 128 * k;
            const int w0  = 2 * idx;
            const int w1  = w0 + 1;

            int hi0 = w0 + HALF_K; if (hi0 > WB - 1) hi0 = WB - 1;
            const int lo0 = w0 - HALF_K - 1;
            float2 u10 = sPa[PAD8(hi0)], u20 = sPb[PAD8(hi0)];
            if (lo0 >= 0) {
                float2 q1 = sPa[PAD8(lo0)], q2 = sPb[PAD8(lo0)];
                u10.x -= q1.x; u10.y -= q1.y; u20.x -= q2.x; u20.y -= q2.y;
            }
            int hi1 = w1 + HALF_K; if (hi1 > WB - 1) hi1 = WB - 1;
            const int lo1 = w1 - HALF_K - 1;
            float2 u11 = sPa[PAD8(hi1)], u21 = sPb[PAD8(hi1)];
            if (lo1 >= 0) {
                float2 q1 = sPa[PAD8(lo1)], q2 = sPb[PAD8(lo1)];
                u11.x -= q1.x; u11.y -= q1.y; u21.x -= q2.x; u21.y -= q2.y;
            }
            ud[idx] = make_uint4(f2h(u10.x, u10.y), f2h(u20.x, u20.y),
                                 f2h(u11.x, u11.y), f2h(u21.x, u21.y));
        }
    }
}

// ------- Pass C: vertical sliding sums of u; result = out * rsqrt(var) ---------
// 2 channel-pairs per thread: uint4 u loads, uint2 out loads, float4 res stores.
__global__ void __launch_bounds__(128) pC_vpass(float4* __restrict__ res4)
{
    const int g   = blockIdx.x * 128 + threadIdx.x;   // NB*WH*NSEGC threads
    const int wp  = g & (WH - 1);
    const int nw  = g >> 9;
    const int n   = nw & (NB - 1);
    const int seg = nw >> 3;
    const int r0  = seg * SEGROWSC;
    const int base = (n * HB) * WH + wp;
    const uint4* __restrict__ u4   = reinterpret_cast<const uint4*>(g_u);
    const uint2* __restrict__ out2 = reinterpret_cast<const uint2*>(g_out);

    float s1x0=0.f, s1y0=0.f, s2x0=0.f, s2y0=0.f;
    float s1x1=0.f, s1y1=0.f, s2x1=0.f, s2y1=0.f;
    #pragma unroll 6
    for (int j = 0; j <= 2 * HALF_K; ++j) {
        const int row = r0 - HALF_K - 1 + j;
        if (row >= 0) {
            uint4 p = u4[base + row * WH];
            float2 a = h2f(p.x), b = h2f(p.y), c = h2f(p.z), d = h2f(p.w);
            s1x0 += a.x; s1y0 += a.y; s2x0 += b.x; s2y0 += b.y;
            s1x1 += c.x; s1y1 += c.y; s2x1 += d.x; s2y1 += d.y;
        }
    }

    uint4 avA[CHUNK], svA[CHUNK], avB[CHUNK], svB[CHUNK];
    uint2 ovA[CHUNK], ovB[CHUNK];

    auto loadC = [&](int c, uint4* av, uint4* sv, uint2* ov) {
        #pragma unroll
        for (int q = 0; q < CHUNK; ++q) {
            const int r   = r0 + c + q;
            const int add = r + HALF_K;
            const int sub = r - HALF_K - 1;
            av[q] = (add < HB) ? u4[base + add * WH] : make_uint4(0u,0u,0u,0u);
            sv[q] = (sub >= 0) ? u4[base + sub * WH] : make_uint4(0u,0u,0u,0u);
            ov[q] = out2[base + r * WH];
        }
    };
    auto compC = [&](int c, const uint4* av, const uint4* sv, const uint2* ov) {
        #pragma unroll
        for (int q = 0; q < CHUNK; ++q) {
            {
                float2 a = h2f(av[q].x), b = h2f(av[q].y);
                float2 e = h2f(sv[q].x), f = h2f(sv[q].y);
                s1x0 += a.x - e.x; s1y0 += a.y - e.y;
                s2x0 += b.x - f.x; s2y0 += b.y - f.y;
            }
            {
                float2 a = h2f(av[q].z), b = h2f(av[q].w);
                float2 e = h2f(sv[q].z), f = h2f(sv[q].w);
                s1x1 += a.x - e.x; s1y1 += a.y - e.y;
                s2x1 += b.x - f.x; s2y1 += b.y - f.y;
            }
            const float c1x0 = s1x0 * SCALE_, c1y0 = s1y0 * SCALE_;
            const float c2x0 = s2x0 * SCALE_, c2y0 = s2y0 * SCALE_;
            const float c1x1 = s1x1 * SCALE_, c1y1 = s1y1 * SCALE_;
            const float c2x1 = s2x1 * SCALE_, c2y1 = s2y1 * SCALE_;
            const float ix0 = rsqrtf(fmaxf(c2x0 - c1x0 * c1x0, 1e-14f));
            const float iy0 = rsqrtf(fmaxf(c2y0 - c1y0 * c1y0, 1e-14f));
            const float ix1 = rsqrtf(fmaxf(c2x1 - c1x1 * c1x1, 1e-14f));
            const float iy1 = rsqrtf(fmaxf(c2y1 - c1y1 * c1y1, 1e-14f));
            const float2 o0 = h2f(ov[q].x), o1 = h2f(ov[q].y);
            res4[base + (r0 + c + q) * WH] =
                make_float4(o0.x * ix0, o0.y * iy0, o1.x * ix1, o1.y * iy1);
        }
    };

    loadC(0, avA, svA, ovA);
    #pragma unroll
    for (int c = 0; c < SEGROWSC; c += 2 * CHUNK) {
        loadC(c + CHUNK, avB, svB, ovB);
        compC(c, avA, svA, ovA);
        if (c + 2 * CHUNK < SEGROWSC)
            loadC(c + 2 * CHUNK, avA, svA, ovA);
        compC(c + CHUNK, avB, svB, ovB);
    }
}

extern "C" void kernel_launch(void* const* d_in, const int* in_sizes, int n_in,
                              void* d_out, int out_size)
{
    (void)in_sizes; (void)n_in; (void)out_size;   // filter_size fixed at 61
    const float4* x4 = (const float4*)d_in[0];
    float4* res4 = (float4*)d_out;

    pA_vsum <<<(NB * WH * NSEGA) / 128, 128>>>(x4);
    pB_hscan<<<NB * HB, 128>>>(x4);
    pC_vpass<<<(NB * WH * NSEGC) / 128, 128>>>(res4);
}

// round 13
// speedup vs baseline: 1.1223x; 1.1223x over previous
#include <cuda_runtime.h>
#include <cuda_fp16.h>

// ImageNormalization2D: x (8,1024,1024,2) f32, k=61 box local std-normalization.
// R13: R11 structure restored (16B widening reverted — it halved occupancy and
//   regressed). Warm-up amplification cut instead: NSEGA 32->16, NSEGC 16->8
//   (pA was at the LTS cap with 2.9x warm-up reread of x; now 1.95x / 1.48x).

#define NB 8
#define HB 1024
#define WB 1024
#define HALF_K 30
#define TOT (NB*HB*WB)       // channel-pair elements
#define CHUNK 8

#define NSEGA 16             // pass A segments
#define SEGROWSA (HB / NSEGA)
#define NSEGC 8              // pass C segments
#define SEGROWSC (HB / NSEGC)

static constexpr float SCALE_ = 1.0f / (61.0f * 61.0f * 2.0f);  // 1/(k*k*C)

// Scratch (static device globals; fp16x2 packed in unsigned)
__device__ unsigned g_v1[TOT];    // Vsum(x)                    32 MB
__device__ unsigned g_out[TOT];   // x - box(x)                 32 MB
__device__ uint2    g_u[TOT];     // {Hsum(out), Hsum(out^2)}   64 MB

static __device__ __forceinline__ int pad32(int j) { return j + (j >> 5); }
#define PAD8(j) ((j) + ((j) >> 3))

static __device__ __forceinline__ float2 h2f(unsigned u) {
    __half2 h; *reinterpret_cast<unsigned*>(&h) = u;
    return __half22float2(h);
}
static __device__ __forceinline__ unsigned f2h(float a, float b) {
    __half2 h = __floats2half2_rn(a, b);
    return *reinterpret_cast<unsigned*>(&h);
}

// --------------- Pass A: vertical window sum of x -> v1 (fp16) -----------------
__global__ void __launch_bounds__(128) pA_vsum(const float2* __restrict__ x)
{
    const int g   = blockIdx.x * 128 + threadIdx.x;   // NB*WB*NSEGA threads
    const int w   = g & (WB - 1);
    const int nw  = g >> 10;
    const int n   = nw & (NB - 1);
    const int seg = nw >> 3;
    const int r0  = seg * SEGROWSA;
    const int base = (n * HB) * WB + w;

    // warm-up rows [r0-31, r0+29] (main loop subtracts r-31 BEFORE output at r)
    float sx = 0.f, sy = 0.f;
    #pragma unroll 6
    for (int j = 0; j <= 2 * HALF_K; ++j) {
        const int row = r0 - HALF_K - 1 + j;
        if (row >= 0) {
            float2 v = x[base + row * WB];
            sx += v.x; sy += v.y;
        }
    }

    float2 avA[CHUNK], svA[CHUNK], avB[CHUNK], svB[CHUNK];

    auto loadC = [&](int c, float2* av, float2* sv) {
        #pragma unroll
        for (int q = 0; q < CHUNK; ++q) {
            const int r   = r0 + c + q;
            const int add = r + HALF_K;
            const int sub = r - HALF_K - 1;
            av[q] = (add < HB) ? x[base + add * WB] : make_float2(0.f, 0.f);
            sv[q] = (sub >= 0) ? x[base + sub * WB] : make_float2(0.f, 0.f);
        }
    };
    auto compC = [&](int c, const float2* av, const float2* sv) {
        #pragma unroll
        for (int q = 0; q < CHUNK; ++q) {
            sx += av[q].x - sv[q].x; sy += av[q].y - sv[q].y;
            g_v1[base + (r0 + c + q) * WB] = f2h(sx, sy);
        }
    };

    loadC(0, avA, svA);
    #pragma unroll
    for (int c = 0; c < SEGROWSA; c += 2 * CHUNK) {
        loadC(c + CHUNK, avB, svB);
        compC(c, avA, svA);
        if (c + 2 * CHUNK < SEGROWSA)
            loadC(c + 2 * CHUNK, avA, svA);
        compC(c + CHUNK, avB, svB);
    }
}

// ------ Pass B: scan-based. out = x - Hbox(v1)*scale; u1,u2 = Hbox(out,out^2) --
// One image-row per 128-thread block. Smem ~22.8 KB.
__global__ void __launch_bounds__(128, 8) pB_hscan(const float2* __restrict__ x)
{
    __shared__ float2   sPa[1160];   // P1, then P2   (PAD8: max idx 1150)
    __shared__ float2   sPb[1160];   // P3
    __shared__ unsigned sV[1056];    // v1 stage, then out (fp16)
    __shared__ float2   wsA[4];
    __shared__ float4   wsB[4];

    const int t    = threadIdx.x;       // 0..127
    const int lane = t & 31;
    const int wid  = t >> 5;
    const size_t base = (size_t)blockIdx.x * WB;

    // 1. stage v1 row (coalesced uint2)
    {
        const uint2* src = reinterpret_cast<const uint2*>(g_v1 + base);
        #pragma unroll
        for (int i = 0; i < 4; ++i) {
            const int idx = t + 128 * i;            // 512 uint2
            uint2 v = src[idx];
            const int col = 2 * idx;
            sV[pad32(col)]     = v.x;
            sV[pad32(col + 1)] = v.y;
        }
    }
    __syncthreads();

    // 2. scan v1 -> P1 (sPa). Contiguous ownership: thread t owns [8t, 8t+8).
    {
        float2 pref[8];
        float ax = 0.f, ay = 0.f;
        #pragma unroll
        for (int q = 0; q < 8; ++q) {
            float2 v = h2f(sV[pad32(8 * t + q)]);
            ax += v.x; ay += v.y;
            pref[q] = make_float2(ax, ay);
        }
        float tx = ax, ty = ay;
        #pragma unroll
        for (int d = 1; d < 32; d <<= 1) {
            float ox = __shfl_up_sync(0xffffffffu, tx, d);
            float oy = __shfl_up_sync(0xffffffffu, ty, d);
            if (lane >= d) { tx += ox; ty += oy; }
        }
        if (lane == 31) wsA[wid] = make_float2(tx, ty);
        __syncthreads();
        float bx = tx - ax, by = ty - ay;           // exclusive within warp
        for (int k = 0; k < wid; ++k) { bx += wsA[k].x; by += wsA[k].y; }
        #pragma unroll
        for (int q = 0; q < 8; ++q)
            sPa[PAD8(8 * t + q)] = make_float2(bx + pref[q].x, by + pref[q].y);
    }
    __syncthreads();

    // 3. out = x - window(P1)*scale. Strided ownership: w = t + 128k.
    #pragma unroll
    for (int k = 0; k < 8; ++k) {
        const int w  = t + 128 * k;
        int hi = w + HALF_K; if (hi > WB - 1) hi = WB - 1;
        const int lo = w - HALF_K - 1;
        float2 m = sPa[PAD8(hi)];
        if (lo >= 0) { float2 p = sPa[PAD8(lo)]; m.x -= p.x; m.y -= p.y; }
        float2 xv = x[base + w];
        const unsigned o = f2h(xv.x - m.x * SCALE_, xv.y - m.y * SCALE_);
        g_out[base + w] = o;
        sV[pad32(w)] = o;                            // v1 dead; repurpose
    }
    __syncthreads();

    // 4. dual scan of out, out^2 -> P2 (sPa), P3 (sPb)
    {
        float2 p1[8], p2[8];
        float a1x = 0.f, a1y = 0.f, a2x = 0.f, a2y = 0.f;
        #pragma unroll
        for (int q = 0; q < 8; ++q) {
            float2 v = h2f(sV[pad32(8 * t + q)]);
            a1x += v.x;       a1y += v.y;
            a2x += v.x * v.x; a2y += v.y * v.y;
            p1[q] = make_float2(a1x, a1y);
            p2[q] = make_float2(a2x, a2y);
        }
        float t1x = a1x, t1y = a1y, t2x = a2x, t2y = a2y;
        #pragma unroll
        for (int d = 1; d < 32; d <<= 1) {
            float o1x = __shfl_up_sync(0xffffffffu, t1x, d);
            float o1y = __shfl_up_sync(0xffffffffu, t1y, d);
            float o2x = __shfl_up_sync(0xffffffffu, t2x, d);
            float o2y = __shfl_up_sync(0xffffffffu, t2y, d);
            if (lane >= d) { t1x += o1x; t1y += o1y; t2x += o2x; t2y += o2y; }
        }
        if (lane == 31) wsB[wid] = make_float4(t1x, t1y, t2x, t2y);
        __syncthreads();
        float b1x = t1x - a1x, b1y = t1y - a1y;
        float b2x = t2x - a2x, b2y = t2y - a2y;
        for (int k = 0; k < wid; ++k) {
            float4 s = wsB[k];
            b1x += s.x; b1y += s.y; b2x += s.z; b2y += s.w;
        }
        #pragma unroll
        for (int q = 0; q < 8; ++q) {
            sPa[PAD8(8 * t + q)] = make_float2(b1x + p1[q].x, b1y + p1[q].y);
            sPb[PAD8(8 * t + q)] = make_float2(b2x + p2[q].x, b2y + p2[q].y);
        }
    }
    __syncthreads();

    // 5. u windows -> g_u (STG.64 coalesced)
    #pragma unroll
    for (int k = 0; k < 8; ++k) {
        const int w  = t + 128 * k;
        int hi = w + HALF_K; if (hi > WB - 1) hi = WB - 1;
        const int lo = w - HALF_K - 1;
        float2 u1 = sPa[PAD8(hi)], u2 = sPb[PAD8(hi)];
        if (lo >= 0) {
            float2 q1 = sPa[PAD8(lo)], q2 = sPb[PAD8(lo)];
            u1.x -= q1.x; u1.y -= q1.y; u2.x -= q2.x; u2.y -= q2.y;
        }
        g_u[base + w] = make_uint2(f2h(u1.x, u1.y), f2h(u2.x, u2.y));
    }
}

// ------- Pass C: vertical sliding sums of u; result = out * rsqrt(var) ---------
__global__ void __launch_bounds__(128) pC_vpass(float2* __restrict__ res)
{
    const int g   = blockIdx.x * 128 + threadIdx.x;
    const int w   = g & (WB - 1);
    const int nw  = g >> 10;
    const int n   = nw & (NB - 1);
    const int seg = nw >> 3;
    const int r0  = seg * SEGROWSC;
    const int base = (n * HB) * WB + w;
    const uint2* __restrict__ u = g_u;

    // warm-up rows [r0-31, r0+29]
    float s1x = 0.f, s1y = 0.f, s2x = 0.f, s2y = 0.f;
    #pragma unroll 6
    for (int j = 0; j <= 2 * HALF_K; ++j) {
        const int row = r0 - HALF_K - 1 + j;
        if (row >= 0) {
            uint2 p = u[base + row * WB];
            float2 a = h2f(p.x), b = h2f(p.y);
            s1x += a.x; s1y += a.y; s2x += b.x; s2y += b.y;
        }
    }

    uint2    avA[CHUNK], svA[CHUNK], avB[CHUNK], svB[CHUNK];
    unsigned ovA[CHUNK], ovB[CHUNK];

    auto loadC = [&](int c, uint2* av, uint2* sv, unsigned* ov) {
        #pragma unroll
        for (int q = 0; q < CHUNK; ++q) {
            const int r   = r0 + c + q;
            const int add = r + HALF_K;
            const int sub = r - HALF_K - 1;
            av[q] = (add < HB) ? u[base + add * WB] : make_uint2(0u, 0u);
            sv[q] = (sub >= 0) ? u[base + sub * WB] : make_uint2(0u, 0u);
            ov[q] = g_out[base + r * WB];
        }
    };
    auto compC = [&](int c, const uint2* av, const uint2* sv, const unsigned* ov) {
        #pragma unroll
        for (int q = 0; q < CHUNK; ++q) {
            float2 a1 = h2f(av[q].x), a2 = h2f(av[q].y);
            float2 b1 = h2f(sv[q].x), b2 = h2f(sv[q].y);
            s1x += a1.x - b1.x; s1y += a1.y - b1.y;
            s2x += a2.x - b2.x; s2y += a2.y - b2.y;

            const float c1x = s1x * SCALE_, c1y = s1y * SCALE_;
            const float c2x = s2x * SCALE_, c2y = s2y * SCALE_;
            // 1/(sqrt(d)+1e-7) ~= rsqrt(d): rel diff ~1e-7 (std ~ 1 here)
            const float ix = rsqrtf(fmaxf(c2x - c1x * c1x, 1e-14f));
            const float iy = rsqrtf(fmaxf(c2y - c1y * c1y, 1e-14f));
            const float2 o = h2f(ov[q]);
            res[base + (c + q + r0) * WB] = make_float2(o.x * ix, o.y * iy);
        }
    };

    loadC(0, avA, svA, ovA);
    #pragma unroll
    for (int c = 0; c < SEGROWSC; c += 2 * CHUNK) {
        loadC(c + CHUNK, avB, svB, ovB);
        compC(c, avA, svA, ovA);
        if (c + 2 * CHUNK < SEGROWSC)
            loadC(c + 2 * CHUNK, avA, svA, ovA);
        compC(c + CHUNK, avB, svB, ovB);
    }
}

extern "C" void kernel_launch(void* const* d_in, const int* in_sizes, int n_in,
                              void* d_out, int out_size)
{
    (void)in_sizes; (void)n_in; (void)out_size;   // filter_size fixed at 61
    const float2* x = (const float2*)d_in[0];
    float2* res = (float2*)d_out;

    pA_vsum <<<(NB * WB * NSEGA) / 128, 128>>>(x);
    pB_hscan<<<NB * HB, 128>>>(x);
    pC_vpass<<<(NB * WB * NSEGC) / 128, 128>>>(res);
}